// round 1
// baseline (speedup 1.0000x reference)
#include <cuda_runtime.h>
#include <cuda_bf16.h>
#include <cstdint>

// Problem constants
#define Bq 2
#define Hq 8
#define Sq 2048
#define Dq 64
#define TEMP 8.0f

// Tiling
#define BM 128
#define BN 128
#define NTHREADS 256
#define QS 68            // padded row stride for q/k/v smem (floats)
#define ES (BN + 4)      // padded row stride for exp tile (floats)

// scratch: per-row softmax denominators
__device__ float g_rowsum[Bq * Hq * Sq];

__global__ __launch_bounds__(NTHREADS, 1)
void attn_main_kernel(const float* __restrict__ q,
                      const float* __restrict__ k,
                      const float* __restrict__ v,
                      const float* __restrict__ cov,
                      const float* __restrict__ lambda_w,
                      const int*   __restrict__ mask,
                      float* __restrict__ out,      // [B,H,S,D]
                      float* __restrict__ attn)     // [B,H,S,S] (unnormalized exp)
{
    extern __shared__ float sm[];
    float* q_s = sm;                    // BM x QS
    float* k_s = q_s + BM * QS;         // BN x QS
    float* v_s = k_s + BN * QS;         // BN x QS
    float* e_s = v_s + BN * QS;         // BM x ES

    const int mtile = blockIdx.x;
    const int h     = blockIdx.y;
    const int b     = blockIdx.z;
    const int bh    = b * Hq + h;
    const int tid   = threadIdx.x;
    const int ty    = tid >> 4;   // 0..15
    const int tx    = tid & 15;   // 0..15

    const float lam  = lambda_w[h];
    const float wcov = lam / (lam + 1.0f);
    const float sqk  = 1.0f / ((lam + 1.0f) * TEMP);

    const float* qg    = q    + ((size_t)bh * Sq + (size_t)mtile * BM) * Dq;
    const float* kg    = k    + (size_t)bh * Sq * Dq;
    const float* vg    = v    + (size_t)bh * Sq * Dq;
    const float* covg  = cov  + ((size_t)b * Sq + (size_t)mtile * BM) * Sq;
    const int*   maskg = mask + ((size_t)b * Sq + (size_t)mtile * BM) * Sq;
    float*       attng = attn + ((size_t)bh * Sq + (size_t)mtile * BM) * Sq;
    float*       outg  = out  + ((size_t)bh * Sq + (size_t)mtile * BM) * Dq;

    // ---- load q tile (once) ----
    {
        const int n4 = BM * Dq / 4;  // 2048 float4
        for (int idx = tid; idx < n4; idx += NTHREADS) {
            int row = idx >> 4;            // /16
            int dcol = (idx & 15) << 2;    // *4
            float4 val = *(const float4*)&qg[row * Dq + dcol];
            *(float4*)&q_s[row * QS + dcol] = val;
        }
    }

    float oacc[8][4];
    float rowsum[8];
#pragma unroll
    for (int i = 0; i < 8; i++) {
        rowsum[i] = 0.0f;
#pragma unroll
        for (int j = 0; j < 4; j++) oacc[i][j] = 0.0f;
    }

    for (int nt = 0; nt < Sq / BN; nt++) {
        const int t0 = nt * BN;

        // ---- load k/v tiles ----
        __syncthreads();  // protect smem from previous AV phase
        {
            const int n4 = BN * Dq / 4;
            for (int idx = tid; idx < n4; idx += NTHREADS) {
                int row = idx >> 4;
                int dcol = (idx & 15) << 2;
                float4 kv = *(const float4*)&kg[(size_t)(t0 + row) * Dq + dcol];
                *(float4*)&k_s[row * QS + dcol] = kv;
                float4 vv = *(const float4*)&vg[(size_t)(t0 + row) * Dq + dcol];
                *(float4*)&v_s[row * QS + dcol] = vv;
            }
        }
        __syncthreads();

        // ---- scores: acc[i][j] = q_row(ty+i*16) . k_row(tx+j*16) ----
        float acc[8][8];
#pragma unroll
        for (int i = 0; i < 8; i++)
#pragma unroll
            for (int j = 0; j < 8; j++) acc[i][j] = 0.0f;

#pragma unroll 4
        for (int d = 0; d < Dq; d++) {
            float qf[8], kf[8];
#pragma unroll
            for (int i = 0; i < 8; i++) qf[i] = q_s[(ty + i * 16) * QS + d];
#pragma unroll
            for (int j = 0; j < 8; j++) kf[j] = k_s[(tx + j * 16) * QS + d];
#pragma unroll
            for (int i = 0; i < 8; i++)
#pragma unroll
                for (int j = 0; j < 8; j++)
                    acc[i][j] += qf[i] * kf[j];
        }

        // ---- epilogue: blend cov, mask, exp, write unnormalized attn ----
#pragma unroll
        for (int i = 0; i < 8; i++) {
            const int sl = ty + i * 16;
#pragma unroll
            for (int j = 0; j < 8; j++) {
                const int t = t0 + tx + j * 16;
                float logit = sqk * acc[i][j] + wcov * covg[(size_t)sl * Sq + t];
                int m = maskg[(size_t)sl * Sq + t];
                float e = (m != 0) ? __expf(logit) : 0.0f;
                rowsum[i] += e;
                attng[(size_t)sl * Sq + t] = e;
                e_s[sl * ES + tx + j * 16] = e;
            }
        }
        __syncthreads();

        // ---- AV: oacc[i][c] += sum_t e_s[row][t] * v_s[t][c] ----
#pragma unroll 2
        for (int t = 0; t < BN; t++) {
            float4 vv = *(const float4*)&v_s[t * QS + tx * 4];
            float ef[8];
#pragma unroll
            for (int i = 0; i < 8; i++) ef[i] = e_s[(ty + i * 16) * ES + t];
#pragma unroll
            for (int i = 0; i < 8; i++) {
                oacc[i][0] += ef[i] * vv.x;
                oacc[i][1] += ef[i] * vv.y;
                oacc[i][2] += ef[i] * vv.z;
                oacc[i][3] += ef[i] * vv.w;
            }
        }
    }

    // ---- reduce rowsums across the 16 tx lanes (xor butterfly within 16-lane halves) ----
#pragma unroll
    for (int i = 0; i < 8; i++) {
#pragma unroll
        for (int off = 1; off < 16; off <<= 1)
            rowsum[i] += __shfl_xor_sync(0xffffffffu, rowsum[i], off);
    }

    // ---- write normalized output + save rowsums ----
#pragma unroll
    for (int i = 0; i < 8; i++) {
        const int sl = ty + i * 16;
        const float inv = 1.0f / rowsum[i];
        float4 o;
        o.x = oacc[i][0] * inv;
        o.y = oacc[i][1] * inv;
        o.z = oacc[i][2] * inv;
        o.w = oacc[i][3] * inv;
        *(float4*)&outg[(size_t)sl * Dq + tx * 4] = o;
        if (tx == 0)
            g_rowsum[(size_t)bh * Sq + (size_t)mtile * BM + sl] = rowsum[i];
    }
}

// Scale each attn row by 1/rowsum
__global__ void attn_normalize_kernel(float* __restrict__ attn)
{
    size_t i = (size_t)blockIdx.x * blockDim.x + threadIdx.x;  // float4 index
    size_t row = (i * 4) >> 11;  // element / 2048
    float inv = 1.0f / g_rowsum[row];
    float4 a = ((float4*)attn)[i];
    a.x *= inv; a.y *= inv; a.z *= inv; a.w *= inv;
    ((float4*)attn)[i] = a;
}

extern "C" void kernel_launch(void* const* d_in, const int* in_sizes, int n_in,
                              void* d_out, int out_size)
{
    const float* q    = (const float*)d_in[0];
    const float* k    = (const float*)d_in[1];
    const float* v    = (const float*)d_in[2];
    const float* cov  = (const float*)d_in[3];
    const float* lam  = (const float*)d_in[4];
    const int*   mask = (const int*)d_in[5];

    float* out  = (float*)d_out;                          // [B,H,S,D]
    float* attn = out + (size_t)Bq * Hq * Sq * Dq;        // [B,H,S,S]

    const int smem = (BM * QS + 2 * BN * QS + BM * ES) * (int)sizeof(float);
    cudaFuncSetAttribute(attn_main_kernel,
                         cudaFuncAttributeMaxDynamicSharedMemorySize, smem);

    dim3 grid(Sq / BM, Hq, Bq);  // (16, 8, 2)
    attn_main_kernel<<<grid, NTHREADS, smem>>>(q, k, v, cov, lam, mask, out, attn);

    const size_t total4 = (size_t)Bq * Hq * Sq * Sq / 4;  // 16,777,216
    attn_normalize_kernel<<<(unsigned)(total4 / 256), 256>>>(attn);
}